// round 4
// baseline (speedup 1.0000x reference)
#include <cuda_runtime.h>

#define BBATCH 4
#define NSEQ   256
#define HHEADS 4
#define CDIM   64
#define DIN    256
#define DFF    1024
#define PEH    128
#define BNTOK  1024
#define PLANE  65536
#define TOT    262144

typedef unsigned long long ull;

__device__ __forceinline__ ull pk2(float x, float y) {
    ull r; asm("mov.b64 %0, {%1,%2};" : "=l"(r) : "f"(x), "f"(y)); return r;
}
__device__ __forceinline__ void upk2(ull v, float& x, float& y) {
    asm("mov.b64 {%0,%1}, %2;" : "=f"(x), "=f"(y) : "l"(v));
}
__device__ __forceinline__ ull ffma2(ull a, ull b, ull c) {
    ull d; asm("fma.rn.f32x2 %0, %1, %2, %3;" : "=l"(d) : "l"(a), "l"(b), "l"(c)); return d;
}
__device__ __forceinline__ unsigned f2t(float x) {
    unsigned u; asm("cvt.rna.tf32.f32 %0, %1;" : "=r"(u) : "f"(x)); return u;
}
__device__ __forceinline__ void mma8(float* d,
                                     unsigned a0, unsigned a1, unsigned a2, unsigned a3,
                                     unsigned b0, unsigned b1) {
    asm volatile("mma.sync.aligned.m16n8k8.row.col.f32.tf32.tf32.f32 "
                 "{%0,%1,%2,%3}, {%4,%5,%6,%7}, {%8,%9}, {%0,%1,%2,%3};"
                 : "+f"(d[0]), "+f"(d[1]), "+f"(d[2]), "+f"(d[3])
                 : "r"(a0), "r"(a1), "r"(a2), "r"(a3), "r"(b0), "r"(b1));
}

// ---------------- scratch ----------------------------------------------------
__device__ float g_QKV[BNTOK * 768];
__device__ float g_psum[BBATCH * HHEADS * PLANE];
__device__ float g_merged[TOT];
__device__ float g_res1[TOT];
__device__ float g_out1[TOT];
__device__ float g_res2[TOT];
__device__ float g_ffnh[BNTOK * DFF];
__device__ float g_pe2s[PEH * HHEADS];
__device__ float g_pe2bs[HHEADS];
__device__ float g_red[16];

// ---------------- prep: fold pe2 over channel groups, zero LN accumulators ---
__global__ void prep_k(const float* __restrict__ pe2w, const float* __restrict__ pe2b) {
    int tid = threadIdx.x;
    if (tid < 128) {
        #pragma unroll
        for (int h = 0; h < 4; h++) {
            float s = 0.f;
            #pragma unroll 8
            for (int c = 0; c < 64; c++) s += pe2w[tid * 256 + h * 64 + c];
            g_pe2s[tid * 4 + h] = s;
        }
    }
    if (tid < 4) {
        float s = 0.f;
        for (int c = 0; c < 64; c++) s += pe2b[tid * 64 + c];
        g_pe2bs[tid] = s;
    }
    if (tid < 16) g_red[tid] = 0.f;
}

// ---------------- PE MLP, folded, 2 rows/thread with f32x2 -------------------
__global__ void pe_k(const float* __restrict__ loc, const float* __restrict__ w1,
                     const float* __restrict__ b1) {
    __shared__ float4 sW[PEH];
    __shared__ ull    sS[PEH][4];
    __shared__ float  sB[4];
    int tid = threadIdx.x;
    if (tid < PEH) {
        sW[tid] = make_float4(b1[tid], w1[tid], w1[PEH + tid], w1[2 * PEH + tid]);
        float4 sv = *(const float4*)(g_pe2s + tid * 4);
        sS[tid][0] = pk2(sv.x, sv.x);
        sS[tid][1] = pk2(sv.y, sv.y);
        sS[tid][2] = pk2(sv.z, sv.z);
        sS[tid][3] = pk2(sv.w, sv.w);
    }
    if (tid < 4) sB[tid] = g_pe2bs[tid];
    __syncthreads();

    int gid = blockIdx.x * 256 + tid;
    const float2* L = (const float2*)loc;
    float2 l0 = L[3 * gid], l1 = L[3 * gid + 1], l2 = L[3 * gid + 2];
    ull A0 = pk2(sB[0], sB[0]), A1 = pk2(sB[1], sB[1]);
    ull A2 = pk2(sB[2], sB[2]), A3 = pk2(sB[3], sB[3]);
    #pragma unroll 4
    for (int i = 0; i < PEH; i++) {
        float4 w = sW[i];
        float h0 = fmaf(l1.x, w.w, fmaf(l0.y, w.z, fmaf(l0.x, w.y, w.x)));
        float h1 = fmaf(l2.y, w.w, fmaf(l2.x, w.z, fmaf(l1.y, w.y, w.x)));
        h0 = fmaxf(h0, 0.f); h1 = fmaxf(h1, 0.f);
        ull hd = pk2(h0, h1);
        A0 = ffma2(hd, sS[i][0], A0);
        A1 = ffma2(hd, sS[i][1], A1);
        A2 = ffma2(hd, sS[i][2], A2);
        A3 = ffma2(hd, sS[i][3], A3);
    }
    int r0 = 2 * gid;
    int b = r0 >> 16, m = (r0 >> 8) & 255, k2 = (r0 & 255) >> 1;
    float2* P = (float2*)g_psum;
    long base = ((long)b * 4) * 32768 + (long)m * 128 + k2;
    float x, y;
    upk2(A0, x, y); P[base]             = make_float2(x, y);
    upk2(A1, x, y); P[base + 32768]     = make_float2(x, y);
    upk2(A2, x, y); P[base + 2 * 32768] = make_float2(x, y);
    upk2(A3, x, y); P[base + 3 * 32768] = make_float2(x, y);
}

// ---------------- fused attention: scores + psum + softmax + AV --------------
// One block per (b,h, 32 score rows). 256 threads / 8 warps.
// Stage 1: S[32,256] = Krows @ Qrows^T (TF32 MMA, K=64), + psum, *0.125.
// Softmax over 256 cols (cross-warp via smem). Stage 2: O[32,64] = attn @ V.
__global__ void __launch_bounds__(256) attn_k(const float* __restrict__ QKV,
                                              const float* __restrict__ psum,
                                              float* __restrict__ merged) {
    struct S1 { unsigned As[2][16][40]; unsigned Bs[2][16][264]; };
    struct S2 { unsigned As2[32][36]; unsigned Vs[32][72]; };
    __shared__ union { S1 s1; S2 s2; } sm;
    __shared__ float srd[2][8][32];

    int tid = threadIdx.x;
    int w = tid >> 5, lane = tid & 31, g = lane >> 2, t = lane & 3;
    int z = blockIdx.y, b = z >> 2, h = z & 3;
    int row0 = blockIdx.x * 32;

    const float* Abase = QKV + (long)(b * 256 + row0) * 768 + 256 + h * 64;  // K rows
    const float* Bbase = QKV + (long)(b * 256) * 768 + h * 64;               // Q rows

    int aR = tid >> 2, aC = (tid & 3) * 4;          // A loader (tid < 128)
    int bR[4], bC[4];
    #pragma unroll
    for (int i = 0; i < 4; i++) { int s = tid + i * 256; bR[i] = s >> 2; bC[i] = (s & 3) * 4; }
    float4 ra; float4 rb[4];

    auto ldg1 = [&](int kc) {
        if (tid < 128) ra = *(const float4*)(Abase + (long)aR * 768 + kc * 16 + aC);
        #pragma unroll
        for (int i = 0; i < 4; i++)
            rb[i] = *(const float4*)(Bbase + (long)bR[i] * 768 + kc * 16 + bC[i]);
    };
    auto sts1 = [&](int bf) {
        if (tid < 128) {
            sm.s1.As[bf][aC + 0][aR] = f2t(ra.x);
            sm.s1.As[bf][aC + 1][aR] = f2t(ra.y);
            sm.s1.As[bf][aC + 2][aR] = f2t(ra.z);
            sm.s1.As[bf][aC + 3][aR] = f2t(ra.w);
        }
        #pragma unroll
        for (int i = 0; i < 4; i++) {
            sm.s1.Bs[bf][bC[i] + 0][bR[i]] = f2t(rb[i].x);
            sm.s1.Bs[bf][bC[i] + 1][bR[i]] = f2t(rb[i].y);
            sm.s1.Bs[bf][bC[i] + 2][bR[i]] = f2t(rb[i].z);
            sm.s1.Bs[bf][bC[i] + 3][bR[i]] = f2t(rb[i].w);
        }
    };

    float acc[2][4][4] = {};
    int buf = 0;
    ldg1(0); sts1(0); __syncthreads();
    #pragma unroll
    for (int kc = 0; kc < 4; kc++) {
        if (kc < 3) ldg1(kc + 1);
        #pragma unroll
        for (int ks = 0; ks < 2; ks++) {
            unsigned af[2][4];
            #pragma unroll
            for (int mi = 0; mi < 2; mi++) {
                int m0 = mi * 16 + g;
                af[mi][0] = sm.s1.As[buf][ks * 8 + t][m0];
                af[mi][1] = sm.s1.As[buf][ks * 8 + t][m0 + 8];
                af[mi][2] = sm.s1.As[buf][ks * 8 + t + 4][m0];
                af[mi][3] = sm.s1.As[buf][ks * 8 + t + 4][m0 + 8];
            }
            #pragma unroll
            for (int ni = 0; ni < 4; ni++) {
                int n0 = w * 32 + ni * 8 + g;
                unsigned b0 = sm.s1.Bs[buf][ks * 8 + t][n0];
                unsigned b1 = sm.s1.Bs[buf][ks * 8 + t + 4][n0];
                mma8(acc[0][ni], af[0][0], af[0][1], af[0][2], af[0][3], b0, b1);
                mma8(acc[1][ni], af[1][0], af[1][1], af[1][2], af[1][3], b0, b1);
            }
        }
        if (kc < 3) { sts1(buf ^ 1); __syncthreads(); buf ^= 1; }
    }

    // add psum, scale
    const float* pp = psum + (long)z * PLANE;
    #pragma unroll
    for (int mi = 0; mi < 2; mi++)
        #pragma unroll
        for (int ni = 0; ni < 4; ni++)
            #pragma unroll
            for (int half = 0; half < 2; half++) {
                int r = mi * 16 + g + half * 8;
                int c = w * 32 + ni * 8 + 2 * t;
                float2 pv = *(const float2*)(pp + (long)(row0 + r) * 256 + c);
                acc[mi][ni][half * 2]     = (acc[mi][ni][half * 2]     + pv.x) * 0.125f;
                acc[mi][ni][half * 2 + 1] = (acc[mi][ni][half * 2 + 1] + pv.y) * 0.125f;
            }

    // softmax over cols (256) — cross-warp reductions
    float fm[2][2];
    #pragma unroll
    for (int mi = 0; mi < 2; mi++)
        #pragma unroll
        for (int half = 0; half < 2; half++) {
            float m = -1e30f;
            #pragma unroll
            for (int ni = 0; ni < 4; ni++)
                m = fmaxf(m, fmaxf(acc[mi][ni][half * 2], acc[mi][ni][half * 2 + 1]));
            m = fmaxf(m, __shfl_xor_sync(0xffffffffu, m, 1));
            m = fmaxf(m, __shfl_xor_sync(0xffffffffu, m, 2));
            if (t == 0) srd[0][w][mi * 16 + g + half * 8] = m;
        }
    __syncthreads();
    #pragma unroll
    for (int mi = 0; mi < 2; mi++)
        #pragma unroll
        for (int half = 0; half < 2; half++) {
            int r = mi * 16 + g + half * 8;
            float m = srd[0][0][r];
            #pragma unroll
            for (int ww = 1; ww < 8; ww++) m = fmaxf(m, srd[0][ww][r]);
            fm[mi][half] = m;
        }
    float sums[2][2];
    #pragma unroll
    for (int mi = 0; mi < 2; mi++)
        #pragma unroll
        for (int half = 0; half < 2; half++) {
            float s = 0.f;
            #pragma unroll
            for (int ni = 0; ni < 4; ni++) {
                float v0 = __expf(acc[mi][ni][half * 2]     - fm[mi][half]);
                float v1 = __expf(acc[mi][ni][half * 2 + 1] - fm[mi][half]);
                acc[mi][ni][half * 2] = v0; acc[mi][ni][half * 2 + 1] = v1;
                s += v0 + v1;
            }
            s += __shfl_xor_sync(0xffffffffu, s, 1);
            s += __shfl_xor_sync(0xffffffffu, s, 2);
            if (t == 0) srd[1][w][mi * 16 + g + half * 8] = s;
            sums[mi][half] = 0.f;
        }
    __syncthreads();
    #pragma unroll
    for (int mi = 0; mi < 2; mi++)
        #pragma unroll
        for (int half = 0; half < 2; half++) {
            int r = mi * 16 + g + half * 8;
            float s = 0.f;
            #pragma unroll
            for (int ww = 0; ww < 8; ww++) s += srd[1][ww][r];
            float inv = 1.f / s;
            #pragma unroll
            for (int ni = 0; ni < 4; ni++) {
                acc[mi][ni][half * 2]     *= inv;
                acc[mi][ni][half * 2 + 1] *= inv;
            }
            sums[mi][half] = inv; // keep alive (unused)
        }
    __syncthreads();  // stage-1 smem fully retired

    // stage 2: O = attn @ V, 8 chunks of 32 contraction cols
    float accO[2][4] = {};
    int wr2 = w & 1, wc2 = w >> 1;
    const float* Vb0 = QKV + (long)(b * 256) * 768 + 512 + h * 64;
    #pragma unroll 1
    for (int c0 = 0; c0 < 8; c0++) {
        if (w == c0) {
            #pragma unroll
            for (int mi = 0; mi < 2; mi++)
                #pragma unroll
                for (int half = 0; half < 2; half++) {
                    int r = mi * 16 + g + half * 8;
                    #pragma unroll
                    for (int ni = 0; ni < 4; ni++) {
                        sm.s2.As2[r][ni * 8 + 2 * t]     = f2t(acc[mi][ni][half * 2]);
                        sm.s2.As2[r][ni * 8 + 2 * t + 1] = f2t(acc[mi][ni][half * 2 + 1]);
                    }
                }
        }
        #pragma unroll
        for (int i = 0; i < 2; i++) {
            int s = tid + i * 256;
            int vR = s >> 4, vC = (s & 15) * 4;
            float4 v = *(const float4*)(Vb0 + (long)(c0 * 32 + vR) * 768 + vC);
            sm.s2.Vs[vR][vC + 0] = f2t(v.x);
            sm.s2.Vs[vR][vC + 1] = f2t(v.y);
            sm.s2.Vs[vR][vC + 2] = f2t(v.z);
            sm.s2.Vs[vR][vC + 3] = f2t(v.w);
        }
        __syncthreads();
        #pragma unroll
        for (int ks = 0; ks < 4; ks++) {
            int k0 = ks * 8;
            unsigned a0 = sm.s2.As2[wr2 * 16 + g][k0 + t];
            unsigned a1 = sm.s2.As2[wr2 * 16 + g + 8][k0 + t];
            unsigned a2 = sm.s2.As2[wr2 * 16 + g][k0 + t + 4];
            unsigned a3 = sm.s2.As2[wr2 * 16 + g + 8][k0 + t + 4];
            #pragma unroll
            for (int ni = 0; ni < 2; ni++) {
                int n0 = wc2 * 16 + ni * 8 + g;
                unsigned b0 = sm.s2.Vs[k0 + t][n0];
                unsigned b1 = sm.s2.Vs[k0 + t + 4][n0];
                mma8(accO[ni], a0, a1, a2, a3, b0, b1);
            }
        }
        __syncthreads();
    }

    #pragma unroll
    for (int ni = 0; ni < 2; ni++)
        #pragma unroll
        for (int half = 0; half < 2; half++) {
            int r = row0 + wr2 * 16 + g + half * 8;
            int c = h * 64 + wc2 * 16 + ni * 8 + 2 * t;
            *(float2*)(merged + (long)(b * 256 + r) * 256 + c) =
                make_float2(accO[ni][half * 2], accO[ni][half * 2 + 1]);
        }
}

// ---------------- TF32 GEMM, NN, BM=BN=64, BK=32, 128 thr --------------------
#define EPI_BIAS  0
#define EPI_BRELU 1
#define EPI_BRR   2

template<int EPI, int SRC3>
__global__ void gtc(const float* __restrict__ A,
                    const float* __restrict__ B0, const float* __restrict__ B1,
                    const float* __restrict__ B2,
                    const float* __restrict__ bias0, const float* __restrict__ bias1,
                    const float* __restrict__ bias2,
                    const float* __restrict__ R, float* __restrict__ C,
                    float* __restrict__ red,
                    int K, int lda, int ldb, int ldc) {
    constexpr int BM = 64, BN = 64, BK = 32, NTHR = 128;
    constexpr int APT = BM * BK / 4 / NTHR;  // 4
    constexpr int BPT = BN * BK / 4 / NTHR;  // 4
    __shared__ unsigned As[2][BK][BM + 8];
    __shared__ unsigned Bs[2][BK][BN + 8];
    __shared__ float shr[2][4];

    int tid = threadIdx.x, w = tid >> 5, lane = tid & 31;
    int g = lane >> 2, t = lane & 3;
    int wr = w & 1, wc = w >> 1;

    const float* B = B0;
    const float* bias = bias0;
    int bcol0 = blockIdx.x * BN;
    if (SRC3) {
        int sel = blockIdx.x >> 2;
        B = (sel == 0) ? B0 : (sel == 1 ? B1 : B2);
        bias = (sel == 0) ? bias0 : (sel == 1 ? bias1 : bias2);
        bcol0 = (blockIdx.x & 3) * BN;
    }
    const float* Ab = A + (long)(blockIdx.y * BM) * lda;
    const float* Bb = B + bcol0;

    int aR[APT], aC[APT], bRr[BPT], bCc[BPT];
    #pragma unroll
    for (int i = 0; i < APT; i++) {
        int s = tid + i * NTHR;
        aR[i] = s / (BK / 4); aC[i] = (s % (BK / 4)) * 4;
    }
    #pragma unroll
    for (int i = 0; i < BPT; i++) {
        int s = tid + i * NTHR;
        bRr[i] = s / (BN / 4); bCc[i] = (s % (BN / 4)) * 4;
    }
    float4 rA[APT], rB[BPT];

    auto ldg = [&](int kt) {
        int kb = kt * BK;
        #pragma unroll
        for (int i = 0; i < APT; i++)
            rA[i] = *(const float4*)(Ab + (long)aR[i] * lda + kb + aC[i]);
        #pragma unroll
        for (int i = 0; i < BPT; i++)
            rB[i] = *(const float4*)(Bb + (long)(kb + bRr[i]) * ldb + bCc[i]);
    };
    auto sts = [&](int bf) {
        #pragma unroll
        for (int i = 0; i < APT; i++) {
            float4 v = rA[i];
            As[bf][aC[i] + 0][aR[i]] = f2t(v.x);
            As[bf][aC[i] + 1][aR[i]] = f2t(v.y);
            As[bf][aC[i] + 2][aR[i]] = f2t(v.z);
            As[bf][aC[i] + 3][aR[i]] = f2t(v.w);
        }
        #pragma unroll
        for (int i = 0; i < BPT; i++) {
            float4 v = rB[i];
            *(uint4*)&Bs[bf][bRr[i]][bCc[i]] =
                make_uint4(f2t(v.x), f2t(v.y), f2t(v.z), f2t(v.w));
        }
    };

    float acc[2][4][4] = {};
    int wm = wr * 32, wn = wc * 32;
    int KT = K / BK, buf = 0;

    ldg(0); sts(0); __syncthreads();
    for (int kt = 0; kt < KT; kt++) {
        if (kt + 1 < KT) ldg(kt + 1);
        #pragma unroll
        for (int ks = 0; ks < BK / 8; ks++) {
            unsigned af[2][4], bfr[4][2];
            #pragma unroll
            for (int mi = 0; mi < 2; mi++) {
                int m0 = wm + mi * 16 + g;
                af[mi][0] = As[buf][ks * 8 + t][m0];
                af[mi][1] = As[buf][ks * 8 + t][m0 + 8];
                af[mi][2] = As[buf][ks * 8 + t + 4][m0];
                af[mi][3] = As[buf][ks * 8 + t + 4][m0 + 8];
            }
            #pragma unroll
            for (int ni = 0; ni < 4; ni++) {
                int n0 = wn + ni * 8 + g;
                bfr[ni][0] = Bs[buf][ks * 8 + t][n0];
                bfr[ni][1] = Bs[buf][ks * 8 + t + 4][n0];
            }
            #pragma unroll
            for (int mi = 0; mi < 2; mi++)
                #pragma unroll
                for (int ni = 0; ni < 4; ni++)
                    mma8(acc[mi][ni], af[mi][0], af[mi][1], af[mi][2], af[mi][3],
                         bfr[ni][0], bfr[ni][1]);
        }
        if (kt + 1 < KT) { sts(buf ^ 1); __syncthreads(); buf ^= 1; }
    }

    int row0 = blockIdx.y * BM + wm;
    int ocol0 = blockIdx.x * BN + wn;
    int bcolw = bcol0 + wn;
    float sum = 0.f, sq = 0.f;
    #pragma unroll
    for (int mi = 0; mi < 2; mi++)
        #pragma unroll
        for (int ni = 0; ni < 4; ni++)
            #pragma unroll
            for (int half = 0; half < 2; half++) {
                int r = row0 + mi * 16 + g + half * 8;
                int cl = ni * 8 + 2 * t;
                float x = acc[mi][ni][half * 2], y = acc[mi][ni][half * 2 + 1];
                float2 bv = *(const float2*)(bias + bcolw + cl);
                long idx = (long)r * ldc + ocol0 + cl;
                if (EPI == EPI_BIAS)  { x += bv.x; y += bv.y; }
                if (EPI == EPI_BRELU) { x = fmaxf(x + bv.x, 0.f); y = fmaxf(y + bv.y, 0.f); }
                if (EPI == EPI_BRR) {
                    float2 rv = *(const float2*)(R + idx);
                    x += bv.x + rv.x; y += bv.y + rv.y;
                    sum += x + y; sq += x * x + y * y;
                }
                *(float2*)(C + idx) = make_float2(x, y);
            }
    if (EPI == EPI_BRR) {
        #pragma unroll
        for (int o = 16; o > 0; o >>= 1) {
            sum += __shfl_xor_sync(0xffffffffu, sum, o);
            sq  += __shfl_xor_sync(0xffffffffu, sq, o);
        }
        if (lane == 0) { shr[0][w] = sum; shr[1][w] = sq; }
        __syncthreads();
        if (tid == 0) {
            float ts = shr[0][0] + shr[0][1] + shr[0][2] + shr[0][3];
            float tq = shr[1][0] + shr[1][1] + shr[1][2] + shr[1][3];
            int bat = (blockIdx.y * BM) >> 8;
            atomicAdd(&red[bat * 2], ts);
            atomicAdd(&red[bat * 2 + 1], tq);
        }
    }
}

// ---------------- LayerNorm apply --------------------------------------------
__global__ void ln_k(const float* __restrict__ X, const float* __restrict__ w,
                     const float* __restrict__ b, const float* __restrict__ red,
                     float* __restrict__ out) {
    int gid = blockIdx.x * blockDim.x + threadIdx.x;   // < 65536 float4s
    int bt = gid >> 14;
    float m   = red[bt * 2] * (1.f / 65536.f);
    float var = red[bt * 2 + 1] * (1.f / 65536.f) - m * m;
    float ri  = rsqrtf(var + 1e-5f);
    int p = gid & 16383;
    float4 x  = ((const float4*)X)[gid];
    float4 wv = ((const float4*)w)[p];
    float4 bv = ((const float4*)b)[p];
    float4 o;
    o.x = (x.x - m) * ri * wv.x + bv.x;
    o.y = (x.y - m) * ri * wv.y + bv.y;
    o.z = (x.z - m) * ri * wv.z + bv.z;
    o.w = (x.w - m) * ri * wv.w + bv.w;
    ((float4*)out)[gid] = o;
}

// ---------------- launch ------------------------------------------------------
extern "C" void kernel_launch(void* const* d_in, const int* in_sizes, int n_in,
                              void* d_out, int out_size) {
    const float* feat = (const float*)d_in[0];
    const float* loc  = (const float*)d_in[1];
    const float* Kw   = (const float*)d_in[2];
    const float* Kb   = (const float*)d_in[3];
    const float* Qw   = (const float*)d_in[4];
    const float* Qb   = (const float*)d_in[5];
    const float* Vw   = (const float*)d_in[6];
    const float* Vb   = (const float*)d_in[7];
    const float* Fw   = (const float*)d_in[8];
    const float* Fb   = (const float*)d_in[9];
    const float* pe1w = (const float*)d_in[10];
    const float* pe1b = (const float*)d_in[11];
    const float* pe2w = (const float*)d_in[12];
    const float* pe2b = (const float*)d_in[13];
    const float* f1w  = (const float*)d_in[14];
    const float* f1b  = (const float*)d_in[15];
    const float* f2w  = (const float*)d_in[16];
    const float* f2b  = (const float*)d_in[17];
    const float* ln1w = (const float*)d_in[18];
    const float* ln1b = (const float*)d_in[19];
    const float* ln2w = (const float*)d_in[20];
    const float* ln2b = (const float*)d_in[21];
    float* out = (float*)d_out;

    float *pQKV, *pPsum, *pMerged, *pRes1, *pOut1, *pRes2, *pFfnh, *pRed;
    cudaGetSymbolAddress((void**)&pQKV, g_QKV);
    cudaGetSymbolAddress((void**)&pPsum, g_psum);
    cudaGetSymbolAddress((void**)&pMerged, g_merged);
    cudaGetSymbolAddress((void**)&pRes1, g_res1);
    cudaGetSymbolAddress((void**)&pOut1, g_out1);
    cudaGetSymbolAddress((void**)&pRes2, g_res2);
    cudaGetSymbolAddress((void**)&pFfnh, g_ffnh);
    cudaGetSymbolAddress((void**)&pRed, g_red);

    // prep (fold pe2, zero LN stats), PE MLP
    prep_k<<<1, 128>>>(pe2w, pe2b);
    pe_k<<<512, 256>>>(loc, pe1w, pe1b);

    // fused QKV: [1024,256] @ {Qw|Kw|Vw} -> g_QKV[1024,768]
    gtc<EPI_BIAS, 1><<<dim3(12, 16), 128>>>(
        feat, Qw, Kw, Vw, Qb, Kb, Vb, nullptr, pQKV, nullptr,
        256, 256, 256, 768);

    // fused attention
    attn_k<<<dim3(8, 16), 256>>>(pQKV, pPsum, pMerged);

    // output projection + bias + residual + LN1 stats
    gtc<EPI_BRR, 0><<<dim3(4, 16), 128>>>(
        pMerged, Fw, nullptr, nullptr, Fb, nullptr, nullptr, feat, pRes1, pRed,
        256, 256, 256, 256);
    ln_k<<<256, 256>>>(pRes1, ln1w, ln1b, pRed, pOut1);

    // FFN
    gtc<EPI_BRELU, 0><<<dim3(16, 16), 128>>>(
        pOut1, f1w, nullptr, nullptr, f1b, nullptr, nullptr, nullptr, pFfnh, nullptr,
        256, 256, 1024, 1024);
    gtc<EPI_BRR, 0><<<dim3(4, 16), 128>>>(
        pFfnh, f2w, nullptr, nullptr, f2b, nullptr, nullptr, pOut1, pRes2, pRed + 8,
        1024, 1024, 256, 256);
    ln_k<<<256, 256>>>(pRes2, ln2w, ln2b, pRed + 8, out);
}